// round 9
// baseline (speedup 1.0000x reference)
#include <cuda_runtime.h>
#include <cstdint>

#define NT 16     // NUM_TYPES
#define OD 128    // OUT_DIM
#define N_MAX 100000

// Scratch (allocation-free rule: __device__ globals). 16B-aligned for float4.
// g_p is stored PERMUTED within each 16-float row: position h*2+0 holds
// logical element h, position h*2+1 holds logical element h+8 (h=0..7).
// With 8 lanes per edge in scatter, RED #j across lanes covers 32 CONTIGUOUS
// bytes of msum = exactly 1 sector -> 2 atomic sectors/edge total.
__device__ __align__(16) float g_p[N_MAX * NT];
__device__ __align__(16) float g_msum[N_MAX * NT];   // natural layout
__device__ int g_idx64;   // 1 if indices are int64, 0 if int32

// ---------------------------------------------------------------------------
// Init: detect index width + zero msum (float4 stores).
// int32 data misread as int64 gives values >= 2^32 with overwhelming
// probability (hi half would be a random node id, rarely 0).
// ---------------------------------------------------------------------------
__global__ void k_init(const void* __restrict__ src, int E, int n) {
    int i = blockIdx.x * blockDim.x + threadIdx.x;
    if (i == 0) {
        const unsigned long long* p = (const unsigned long long*)src;
        int is64 = 1;
        int lim = (E / 2 < 16) ? E / 2 : 16;
        for (int k = 0; k < lim; k++) {
            if (p[k] > 0x7FFFFFFFULL) is64 = 0;
        }
        g_idx64 = is64;
    }
    int tot4 = n * 4;   // n*16 floats = n*4 float4
    if (i < tot4) ((float4*)g_msum)[i] = make_float4(0.f, 0.f, 0.f, 0.f);
}

// ---------------------------------------------------------------------------
// p = softmax(relu(r@W1+b1) @ Wp + bp)   TWO nodes per thread
// Output stored in the pairwise-permuted layout (see g_p comment).
// ---------------------------------------------------------------------------
__global__ void __launch_bounds__(128) k_compute_p(
        const float* __restrict__ r,
        const float* __restrict__ W1,
        const float* __restrict__ b1,
        const float* __restrict__ Wp,
        const float* __restrict__ bp,
        int n) {
    __shared__ float sW1t[OD * NT];  // [j*16 + k] = W1[k*128 + j]
    __shared__ float sWp [OD * NT];  // [j*16 + t] = Wp[j*16 + t]
    __shared__ float sb1 [OD];
    __shared__ float sbp [NT];

    for (int i = threadIdx.x; i < OD * NT; i += blockDim.x) {
        int j = i >> 4, k = i & 15;
        sW1t[i] = W1[k * OD + j];
        sWp[i]  = Wp[i];
    }
    for (int i = threadIdx.x; i < OD; i += blockDim.x) sb1[i] = b1[i];
    if (threadIdx.x < NT) sbp[threadIdx.x] = bp[threadIdx.x];
    __syncthreads();

    int node0 = (blockIdx.x * blockDim.x + threadIdx.x) * 2;
    if (node0 >= n) return;
    bool two = (node0 + 1 < n);

    const float4* rp0 = (const float4*)(r + (size_t)node0 * NT);
    float4 a0 = rp0[0], a1 = rp0[1], a2 = rp0[2], a3 = rp0[3];
    float4 b0, b1v, b2, b3;
    if (two) {
        const float4* rp1 = (const float4*)(r + (size_t)(node0 + 1) * NT);
        b0 = rp1[0]; b1v = rp1[1]; b2 = rp1[2]; b3 = rp1[3];
    } else {
        b0 = b1v = b2 = b3 = make_float4(0.f, 0.f, 0.f, 0.f);
    }

    float accA[NT], accB[NT];
#pragma unroll
    for (int t = 0; t < NT; t++) { accA[t] = sbp[t]; accB[t] = sbp[t]; }

    const float4* w1t4 = (const float4*)sW1t;
    const float4* wp4  = (const float4*)sWp;

#pragma unroll 2
    for (int j = 0; j < OD; j++) {
        float4 wa = w1t4[j * 4 + 0];
        float4 wb = w1t4[j * 4 + 1];
        float4 wc = w1t4[j * 4 + 2];
        float4 wd = w1t4[j * 4 + 3];
        float bj = sb1[j];

        float zA = bj, zB = bj;
        zA = fmaf(a0.x, wa.x, zA); zA = fmaf(a0.y, wa.y, zA);
        zA = fmaf(a0.z, wa.z, zA); zA = fmaf(a0.w, wa.w, zA);
        zA = fmaf(a1.x, wb.x, zA); zA = fmaf(a1.y, wb.y, zA);
        zA = fmaf(a1.z, wb.z, zA); zA = fmaf(a1.w, wb.w, zA);
        zA = fmaf(a2.x, wc.x, zA); zA = fmaf(a2.y, wc.y, zA);
        zA = fmaf(a2.z, wc.z, zA); zA = fmaf(a2.w, wc.w, zA);
        zA = fmaf(a3.x, wd.x, zA); zA = fmaf(a3.y, wd.y, zA);
        zA = fmaf(a3.z, wd.z, zA); zA = fmaf(a3.w, wd.w, zA);
        zA = fmaxf(zA, 0.0f);

        zB = fmaf(b0.x, wa.x, zB); zB = fmaf(b0.y, wa.y, zB);
        zB = fmaf(b0.z, wa.z, zB); zB = fmaf(b0.w, wa.w, zB);
        zB = fmaf(b1v.x, wb.x, zB); zB = fmaf(b1v.y, wb.y, zB);
        zB = fmaf(b1v.z, wb.z, zB); zB = fmaf(b1v.w, wb.w, zB);
        zB = fmaf(b2.x, wc.x, zB); zB = fmaf(b2.y, wc.y, zB);
        zB = fmaf(b2.z, wc.z, zB); zB = fmaf(b2.w, wc.w, zB);
        zB = fmaf(b3.x, wd.x, zB); zB = fmaf(b3.y, wd.y, zB);
        zB = fmaf(b3.z, wd.z, zB); zB = fmaf(b3.w, wd.w, zB);
        zB = fmaxf(zB, 0.0f);

        float4 p0 = wp4[j * 4 + 0];
        float4 p1 = wp4[j * 4 + 1];
        float4 p2 = wp4[j * 4 + 2];
        float4 p3 = wp4[j * 4 + 3];
        accA[0]  = fmaf(zA, p0.x, accA[0]);  accB[0]  = fmaf(zB, p0.x, accB[0]);
        accA[1]  = fmaf(zA, p0.y, accA[1]);  accB[1]  = fmaf(zB, p0.y, accB[1]);
        accA[2]  = fmaf(zA, p0.z, accA[2]);  accB[2]  = fmaf(zB, p0.z, accB[2]);
        accA[3]  = fmaf(zA, p0.w, accA[3]);  accB[3]  = fmaf(zB, p0.w, accB[3]);
        accA[4]  = fmaf(zA, p1.x, accA[4]);  accB[4]  = fmaf(zB, p1.x, accB[4]);
        accA[5]  = fmaf(zA, p1.y, accA[5]);  accB[5]  = fmaf(zB, p1.y, accB[5]);
        accA[6]  = fmaf(zA, p1.z, accA[6]);  accB[6]  = fmaf(zB, p1.z, accB[6]);
        accA[7]  = fmaf(zA, p1.w, accA[7]);  accB[7]  = fmaf(zB, p1.w, accB[7]);
        accA[8]  = fmaf(zA, p2.x, accA[8]);  accB[8]  = fmaf(zB, p2.x, accB[8]);
        accA[9]  = fmaf(zA, p2.y, accA[9]);  accB[9]  = fmaf(zB, p2.y, accB[9]);
        accA[10] = fmaf(zA, p2.z, accA[10]); accB[10] = fmaf(zB, p2.z, accB[10]);
        accA[11] = fmaf(zA, p2.w, accA[11]); accB[11] = fmaf(zB, p2.w, accB[11]);
        accA[12] = fmaf(zA, p3.x, accA[12]); accB[12] = fmaf(zB, p3.x, accB[12]);
        accA[13] = fmaf(zA, p3.y, accA[13]); accB[13] = fmaf(zB, p3.y, accB[13]);
        accA[14] = fmaf(zA, p3.z, accA[14]); accB[14] = fmaf(zB, p3.z, accB[14]);
        accA[15] = fmaf(zA, p3.w, accA[15]); accB[15] = fmaf(zB, p3.w, accB[15]);
    }

    {
        float m = accA[0];
#pragma unroll
        for (int t = 1; t < NT; t++) m = fmaxf(m, accA[t]);
        float s = 0.0f;
#pragma unroll
        for (int t = 0; t < NT; t++) { accA[t] = __expf(accA[t] - m); s += accA[t]; }
        float inv = 1.0f / s;
        float4* o = (float4*)(g_p + (size_t)node0 * NT);
        // PAIRWISE-PERMUTED store: position h*2 = p[h], h*2+1 = p[h+8]
        o[0] = make_float4(accA[0]*inv, accA[8]*inv,  accA[1]*inv, accA[9]*inv);
        o[1] = make_float4(accA[2]*inv, accA[10]*inv, accA[3]*inv, accA[11]*inv);
        o[2] = make_float4(accA[4]*inv, accA[12]*inv, accA[5]*inv, accA[13]*inv);
        o[3] = make_float4(accA[6]*inv, accA[14]*inv, accA[7]*inv, accA[15]*inv);
    }
    if (two) {
        float m = accB[0];
#pragma unroll
        for (int t = 1; t < NT; t++) m = fmaxf(m, accB[t]);
        float s = 0.0f;
#pragma unroll
        for (int t = 0; t < NT; t++) { accB[t] = __expf(accB[t] - m); s += accB[t]; }
        float inv = 1.0f / s;
        float4* o = (float4*)(g_p + (size_t)(node0 + 1) * NT);
        o[0] = make_float4(accB[0]*inv, accB[8]*inv,  accB[1]*inv, accB[9]*inv);
        o[1] = make_float4(accB[2]*inv, accB[10]*inv, accB[3]*inv, accB[11]*inv);
        o[2] = make_float4(accB[4]*inv, accB[12]*inv, accB[5]*inv, accB[13]*inv);
        o[3] = make_float4(accB[6]*inv, accB[14]*inv, accB[7]*inv, accB[15]*inv);
    }
}

// ---------------------------------------------------------------------------
// Scatter: msum[dst] += p[src].  EIGHT lanes per edge, float2 gather.
// Lane h loads permuted float2 = {p[h], p[h+8]} (8B contiguous; 64B/edge
// across 8 lanes = 2 sectors). RED #0 across lanes writes msum elements
// 0..7 (d*64+h*4: 32 CONTIGUOUS bytes = 1 sector); RED #1 writes elements
// 8..15 (1 sector). -> 2 atomic sectors/edge (was 4 in R8).
// No degree atomics (row-sum trick).
// ---------------------------------------------------------------------------
__global__ void k_scatter(const void* __restrict__ srcv,
                          const void* __restrict__ dstv,
                          int E, int n) {
    int gid = blockIdx.x * blockDim.x + threadIdx.x;
    int e = gid >> 3;
    if (e >= E) return;
    int h = gid & 7;

    int s, d;
    if (g_idx64) {
        s = (int)((const long long*)srcv)[e];
        d = (int)((const long long*)dstv)[e];
    } else {
        s = ((const int*)srcv)[e];
        d = ((const int*)dstv)[e];
    }
    s = min(max(s, 0), n - 1);
    d = min(max(d, 0), n - 1);

    const float2 v = __ldg((const float2*)(g_p + (size_t)s * NT + h * 2));
    float* row = g_msum + (size_t)d * NT + h;
    atomicAdd(row,     v.x);   // logical element h      (sector 0 of row)
    atomicAdd(row + 8, v.y);   // logical element h + 8  (sector 1 of row)
}

// ---------------------------------------------------------------------------
// Normalize: msum[node] *= 1/max(round(rowsum),1).  4 threads per node,
// rowsum via 2 butterfly shuffles. Folds the mean division into msum so
// k_final needs no degree math.
// ---------------------------------------------------------------------------
__global__ void k_norm(int n) {
    int gid = blockIdx.x * blockDim.x + threadIdx.x;
    int node = gid >> 2;
    if (node >= n) return;
    int q = gid & 3;

    float4* p = (float4*)g_msum + (size_t)node * 4 + q;
    float4 v = *p;
    float s = (v.x + v.y) + (v.z + v.w);
    s += __shfl_xor_sync(0xffffffffu, s, 1);
    s += __shfl_xor_sync(0xffffffffu, s, 2);
    float invd = 1.0f / fmaxf(nearbyintf(s), 1.0f);
    v.x *= invd; v.y *= invd; v.z *= invd; v.w *= invd;
    *p = v;
}

// ---------------------------------------------------------------------------
// out = relu(n_dist @ Wf + bf)   (n_dist = pre-normalized msum)
// j = tid&127 is loop-invariant: the 16 weights live in REGISTERS.
// ---------------------------------------------------------------------------
__global__ void __launch_bounds__(256) k_final(
        const float* __restrict__ Wf,
        const float* __restrict__ bf,
        float* __restrict__ out,
        int n) {
    int j = threadIdx.x & 127;
    float w[NT];
#pragma unroll
    for (int t = 0; t < NT; t++) w[t] = Wf[t * OD + j];   // coalesced, L1-hot
    float bj = bf[j];

    int total  = n * OD;
    int stride = gridDim.x * blockDim.x;   // 3200*256 multiple of 128
    for (int gid = blockIdx.x * blockDim.x + threadIdx.x; gid < total; gid += stride) {
        int node = gid >> 7;

        const float4* ms = (const float4*)(g_msum + (size_t)node * NT);
        float4 m0 = ms[0], m1 = ms[1], m2 = ms[2], m3 = ms[3];

        float acc = bj;
        acc = fmaf(m0.x, w[0],  acc); acc = fmaf(m0.y, w[1],  acc);
        acc = fmaf(m0.z, w[2],  acc); acc = fmaf(m0.w, w[3],  acc);
        acc = fmaf(m1.x, w[4],  acc); acc = fmaf(m1.y, w[5],  acc);
        acc = fmaf(m1.z, w[6],  acc); acc = fmaf(m1.w, w[7],  acc);
        acc = fmaf(m2.x, w[8],  acc); acc = fmaf(m2.y, w[9],  acc);
        acc = fmaf(m2.z, w[10], acc); acc = fmaf(m2.w, w[11], acc);
        acc = fmaf(m3.x, w[12], acc); acc = fmaf(m3.y, w[13], acc);
        acc = fmaf(m3.z, w[14], acc); acc = fmaf(m3.w, w[15], acc);

        out[gid] = fmaxf(acc, 0.0f);
    }
}

// ---------------------------------------------------------------------------
// Inputs (metadata order): r, src, dst, W1, b1, Wp, bp, Wf, bf
// ---------------------------------------------------------------------------
extern "C" void kernel_launch(void* const* d_in, const int* in_sizes, int n_in,
                              void* d_out, int out_size) {
    const float* r   = (const float*)d_in[0];
    const void*  src = d_in[1];
    const void*  dst = d_in[2];
    const float* W1  = (const float*)d_in[3];
    const float* b1  = (const float*)d_in[4];
    const float* Wp  = (const float*)d_in[5];
    const float* bp  = (const float*)d_in[6];
    const float* Wf  = (const float*)d_in[7];
    const float* bf  = (const float*)d_in[8];
    float*       out = (float*)d_out;

    int n = in_sizes[0] / NT;   // N nodes
    int E = in_sizes[1];        // edges
    if (n > N_MAX) n = N_MAX;

    k_init<<<(n * 4 + 255) / 256, 256>>>(src, E, n);
    k_compute_p<<<((n + 1) / 2 + 127) / 128, 128>>>(r, W1, b1, Wp, bp, n);
    {
        long long threads = (long long)E * 8;
        int blocks = (int)((threads + 255) / 256);
        k_scatter<<<blocks, 256>>>(src, dst, E, n);
    }
    k_norm<<<(n * 4 + 255) / 256, 256>>>(n);
    k_final<<<3200, 256>>>(Wf, bf, out, n);
}

// round 10
// speedup vs baseline: 1.1296x; 1.1296x over previous
#include <cuda_runtime.h>
#include <cstdint>

#define NT 16     // NUM_TYPES
#define OD 128    // OUT_DIM
#define N_MAX 100000

// Scratch (allocation-free rule: __device__ globals). 16B-aligned for float4.
// g_p is stored PERMUTED within each 16-float row: position q*4+j holds
// logical element q+4j (q=0..3). Scatter lane q loads float4 #q =
// {p[q], p[q+4], p[q+8], p[q+12]} and REDs to natural msum positions q+4j;
// RED #j across the 4 lanes covers 16 CONTIGUOUS bytes (validated R8: 82.5us).
__device__ __align__(16) float g_p[N_MAX * NT];
__device__ __align__(16) float g_msum[N_MAX * NT];   // natural layout
__device__ int g_idx64;   // 1 if indices are int64, 0 if int32

// ---------------------------------------------------------------------------
// Init: detect index width + zero msum (float4 stores).
// ---------------------------------------------------------------------------
__global__ void k_init(const void* __restrict__ src, int E, int n) {
    int i = blockIdx.x * blockDim.x + threadIdx.x;
    if (i == 0) {
        const unsigned long long* p = (const unsigned long long*)src;
        int is64 = 1;
        int lim = (E / 2 < 16) ? E / 2 : 16;
        for (int k = 0; k < lim; k++) {
            if (p[k] > 0x7FFFFFFFULL) is64 = 0;
        }
        g_idx64 = is64;
    }
    int tot4 = n * 4;   // n*16 floats = n*4 float4
    if (i < tot4) ((float4*)g_msum)[i] = make_float4(0.f, 0.f, 0.f, 0.f);
}

// ---------------------------------------------------------------------------
// p = softmax(relu(r@W1+b1) @ Wp + bp)   TWO nodes per thread
// Output stored in the q/4-permuted layout (see g_p comment).
// ---------------------------------------------------------------------------
__global__ void __launch_bounds__(128) k_compute_p(
        const float* __restrict__ r,
        const float* __restrict__ W1,
        const float* __restrict__ b1,
        const float* __restrict__ Wp,
        const float* __restrict__ bp,
        int n) {
    __shared__ float sW1t[OD * NT];  // [j*16 + k] = W1[k*128 + j]
    __shared__ float sWp [OD * NT];  // [j*16 + t] = Wp[j*16 + t]
    __shared__ float sb1 [OD];
    __shared__ float sbp [NT];

    for (int i = threadIdx.x; i < OD * NT; i += blockDim.x) {
        int j = i >> 4, k = i & 15;
        sW1t[i] = W1[k * OD + j];
        sWp[i]  = Wp[i];
    }
    for (int i = threadIdx.x; i < OD; i += blockDim.x) sb1[i] = b1[i];
    if (threadIdx.x < NT) sbp[threadIdx.x] = bp[threadIdx.x];
    __syncthreads();

    int node0 = (blockIdx.x * blockDim.x + threadIdx.x) * 2;
    if (node0 >= n) return;
    bool two = (node0 + 1 < n);

    const float4* rp0 = (const float4*)(r + (size_t)node0 * NT);
    float4 a0 = rp0[0], a1 = rp0[1], a2 = rp0[2], a3 = rp0[3];
    float4 b0, b1v, b2, b3;
    if (two) {
        const float4* rp1 = (const float4*)(r + (size_t)(node0 + 1) * NT);
        b0 = rp1[0]; b1v = rp1[1]; b2 = rp1[2]; b3 = rp1[3];
    } else {
        b0 = b1v = b2 = b3 = make_float4(0.f, 0.f, 0.f, 0.f);
    }

    float accA[NT], accB[NT];
#pragma unroll
    for (int t = 0; t < NT; t++) { accA[t] = sbp[t]; accB[t] = sbp[t]; }

    const float4* w1t4 = (const float4*)sW1t;
    const float4* wp4  = (const float4*)sWp;

#pragma unroll 2
    for (int j = 0; j < OD; j++) {
        float4 wa = w1t4[j * 4 + 0];
        float4 wb = w1t4[j * 4 + 1];
        float4 wc = w1t4[j * 4 + 2];
        float4 wd = w1t4[j * 4 + 3];
        float bj = sb1[j];

        float zA = bj, zB = bj;
        zA = fmaf(a0.x, wa.x, zA); zA = fmaf(a0.y, wa.y, zA);
        zA = fmaf(a0.z, wa.z, zA); zA = fmaf(a0.w, wa.w, zA);
        zA = fmaf(a1.x, wb.x, zA); zA = fmaf(a1.y, wb.y, zA);
        zA = fmaf(a1.z, wb.z, zA); zA = fmaf(a1.w, wb.w, zA);
        zA = fmaf(a2.x, wc.x, zA); zA = fmaf(a2.y, wc.y, zA);
        zA = fmaf(a2.z, wc.z, zA); zA = fmaf(a2.w, wc.w, zA);
        zA = fmaf(a3.x, wd.x, zA); zA = fmaf(a3.y, wd.y, zA);
        zA = fmaf(a3.z, wd.z, zA); zA = fmaf(a3.w, wd.w, zA);
        zA = fmaxf(zA, 0.0f);

        zB = fmaf(b0.x, wa.x, zB); zB = fmaf(b0.y, wa.y, zB);
        zB = fmaf(b0.z, wa.z, zB); zB = fmaf(b0.w, wa.w, zB);
        zB = fmaf(b1v.x, wb.x, zB); zB = fmaf(b1v.y, wb.y, zB);
        zB = fmaf(b1v.z, wb.z, zB); zB = fmaf(b1v.w, wb.w, zB);
        zB = fmaf(b2.x, wc.x, zB); zB = fmaf(b2.y, wc.y, zB);
        zB = fmaf(b2.z, wc.z, zB); zB = fmaf(b2.w, wc.w, zB);
        zB = fmaf(b3.x, wd.x, zB); zB = fmaf(b3.y, wd.y, zB);
        zB = fmaf(b3.z, wd.z, zB); zB = fmaf(b3.w, wd.w, zB);
        zB = fmaxf(zB, 0.0f);

        float4 p0 = wp4[j * 4 + 0];
        float4 p1 = wp4[j * 4 + 1];
        float4 p2 = wp4[j * 4 + 2];
        float4 p3 = wp4[j * 4 + 3];
        accA[0]  = fmaf(zA, p0.x, accA[0]);  accB[0]  = fmaf(zB, p0.x, accB[0]);
        accA[1]  = fmaf(zA, p0.y, accA[1]);  accB[1]  = fmaf(zB, p0.y, accB[1]);
        accA[2]  = fmaf(zA, p0.z, accA[2]);  accB[2]  = fmaf(zB, p0.z, accB[2]);
        accA[3]  = fmaf(zA, p0.w, accA[3]);  accB[3]  = fmaf(zB, p0.w, accB[3]);
        accA[4]  = fmaf(zA, p1.x, accA[4]);  accB[4]  = fmaf(zB, p1.x, accB[4]);
        accA[5]  = fmaf(zA, p1.y, accA[5]);  accB[5]  = fmaf(zB, p1.y, accB[5]);
        accA[6]  = fmaf(zA, p1.z, accA[6]);  accB[6]  = fmaf(zB, p1.z, accB[6]);
        accA[7]  = fmaf(zA, p1.w, accA[7]);  accB[7]  = fmaf(zB, p1.w, accB[7]);
        accA[8]  = fmaf(zA, p2.x, accA[8]);  accB[8]  = fmaf(zB, p2.x, accB[8]);
        accA[9]  = fmaf(zA, p2.y, accA[9]);  accB[9]  = fmaf(zB, p2.y, accB[9]);
        accA[10] = fmaf(zA, p2.z, accA[10]); accB[10] = fmaf(zB, p2.z, accB[10]);
        accA[11] = fmaf(zA, p2.w, accA[11]); accB[11] = fmaf(zB, p2.w, accB[11]);
        accA[12] = fmaf(zA, p3.x, accA[12]); accB[12] = fmaf(zB, p3.x, accB[12]);
        accA[13] = fmaf(zA, p3.y, accA[13]); accB[13] = fmaf(zB, p3.y, accB[13]);
        accA[14] = fmaf(zA, p3.z, accA[14]); accB[14] = fmaf(zB, p3.z, accB[14]);
        accA[15] = fmaf(zA, p3.w, accA[15]); accB[15] = fmaf(zB, p3.w, accB[15]);
    }

    {
        float m = accA[0];
#pragma unroll
        for (int t = 1; t < NT; t++) m = fmaxf(m, accA[t]);
        float s = 0.0f;
#pragma unroll
        for (int t = 0; t < NT; t++) { accA[t] = __expf(accA[t] - m); s += accA[t]; }
        float inv = 1.0f / s;
        float4* o = (float4*)(g_p + (size_t)node0 * NT);
        // PERMUTED store: float4 #q = {p[q], p[q+4], p[q+8], p[q+12]}
        o[0] = make_float4(accA[0]*inv, accA[4]*inv, accA[8]*inv,  accA[12]*inv);
        o[1] = make_float4(accA[1]*inv, accA[5]*inv, accA[9]*inv,  accA[13]*inv);
        o[2] = make_float4(accA[2]*inv, accA[6]*inv, accA[10]*inv, accA[14]*inv);
        o[3] = make_float4(accA[3]*inv, accA[7]*inv, accA[11]*inv, accA[15]*inv);
    }
    if (two) {
        float m = accB[0];
#pragma unroll
        for (int t = 1; t < NT; t++) m = fmaxf(m, accB[t]);
        float s = 0.0f;
#pragma unroll
        for (int t = 0; t < NT; t++) { accB[t] = __expf(accB[t] - m); s += accB[t]; }
        float inv = 1.0f / s;
        float4* o = (float4*)(g_p + (size_t)(node0 + 1) * NT);
        o[0] = make_float4(accB[0]*inv, accB[4]*inv, accB[8]*inv,  accB[12]*inv);
        o[1] = make_float4(accB[1]*inv, accB[5]*inv, accB[9]*inv,  accB[13]*inv);
        o[2] = make_float4(accB[2]*inv, accB[6]*inv, accB[10]*inv, accB[14]*inv);
        o[3] = make_float4(accB[3]*inv, accB[7]*inv, accB[11]*inv, accB[15]*inv);
    }
}

// ---------------------------------------------------------------------------
// Scatter: msum[dst] += p[src].  4 lanes per edge (R8 pattern, measured
// 82.5us), TWO edges per thread: one longlong2 load fetches both edges'
// indices, cutting preamble issue ~30%. RED #j across an edge's 4 lanes
// covers 16 contiguous bytes (1 sector). No degree atomics (row-sum trick).
// ---------------------------------------------------------------------------
__global__ void k_scatter(const void* __restrict__ srcv,
                          const void* __restrict__ dstv,
                          int E, int n) {
    int gid = blockIdx.x * blockDim.x + threadIdx.x;
    int pair = gid >> 2;          // pair of edges (2*pair, 2*pair+1)
    int e0 = pair * 2;
    if (e0 >= E) return;
    int q = gid & 3;
    bool has2 = (e0 + 1 < E);

    int s0, d0, s1 = 0, d1 = 0;
    if (g_idx64) {
        const longlong2* ps = (const longlong2*)srcv;
        const longlong2* pd = (const longlong2*)dstv;
        longlong2 sv = ps[pair];
        longlong2 dv = pd[pair];
        s0 = (int)sv.x; s1 = (int)sv.y;
        d0 = (int)dv.x; d1 = (int)dv.y;
    } else {
        const int2* ps = (const int2*)srcv;
        const int2* pd = (const int2*)dstv;
        int2 sv = ps[pair];
        int2 dv = pd[pair];
        s0 = sv.x; s1 = sv.y;
        d0 = dv.x; d1 = dv.y;
    }
    s0 = min(max(s0, 0), n - 1);
    d0 = min(max(d0, 0), n - 1);

    const float4 v0 = __ldg((const float4*)(g_p + (size_t)s0 * NT + q * 4));
    float* row0 = g_msum + (size_t)d0 * NT + q;
    atomicAdd(row0 + 0,  v0.x);
    atomicAdd(row0 + 4,  v0.y);
    atomicAdd(row0 + 8,  v0.z);
    atomicAdd(row0 + 12, v0.w);

    if (has2) {
        s1 = min(max(s1, 0), n - 1);
        d1 = min(max(d1, 0), n - 1);
        const float4 v1 = __ldg((const float4*)(g_p + (size_t)s1 * NT + q * 4));
        float* row1 = g_msum + (size_t)d1 * NT + q;
        atomicAdd(row1 + 0,  v1.x);
        atomicAdd(row1 + 4,  v1.y);
        atomicAdd(row1 + 8,  v1.z);
        atomicAdd(row1 + 12, v1.w);
    }
}

// ---------------------------------------------------------------------------
// Normalize: msum[node] *= 1/max(round(rowsum),1).  4 threads per node,
// rowsum via 2 butterfly shuffles (p rows sum to 1 -> rowsum == degree).
// ---------------------------------------------------------------------------
__global__ void k_norm(int n) {
    int gid = blockIdx.x * blockDim.x + threadIdx.x;
    int node = gid >> 2;
    if (node >= n) return;

    float4* p = (float4*)g_msum + (size_t)gid;
    float4 v = *p;
    float s = (v.x + v.y) + (v.z + v.w);
    s += __shfl_xor_sync(0xffffffffu, s, 1);
    s += __shfl_xor_sync(0xffffffffu, s, 2);
    float invd = 1.0f / fmaxf(nearbyintf(s), 1.0f);
    v.x *= invd; v.y *= invd; v.z *= invd; v.w *= invd;
    *p = v;
}

// ---------------------------------------------------------------------------
// out = relu(n_dist @ Wf + bf)   (n_dist = pre-normalized msum)
// j = tid&127 is loop-invariant: the 16 weights live in REGISTERS.
// ---------------------------------------------------------------------------
__global__ void __launch_bounds__(256) k_final(
        const float* __restrict__ Wf,
        const float* __restrict__ bf,
        float* __restrict__ out,
        int n) {
    int j = threadIdx.x & 127;
    float w[NT];
#pragma unroll
    for (int t = 0; t < NT; t++) w[t] = Wf[t * OD + j];   // coalesced, L1-hot
    float bj = bf[j];

    int total  = n * OD;
    int stride = gridDim.x * blockDim.x;   // 3200*256 multiple of 128
    for (int gid = blockIdx.x * blockDim.x + threadIdx.x; gid < total; gid += stride) {
        int node = gid >> 7;

        const float4* ms = (const float4*)(g_msum + (size_t)node * NT);
        float4 m0 = ms[0], m1 = ms[1], m2 = ms[2], m3 = ms[3];

        float acc = bj;
        acc = fmaf(m0.x, w[0],  acc); acc = fmaf(m0.y, w[1],  acc);
        acc = fmaf(m0.z, w[2],  acc); acc = fmaf(m0.w, w[3],  acc);
        acc = fmaf(m1.x, w[4],  acc); acc = fmaf(m1.y, w[5],  acc);
        acc = fmaf(m1.z, w[6],  acc); acc = fmaf(m1.w, w[7],  acc);
        acc = fmaf(m2.x, w[8],  acc); acc = fmaf(m2.y, w[9],  acc);
        acc = fmaf(m2.z, w[10], acc); acc = fmaf(m2.w, w[11], acc);
        acc = fmaf(m3.x, w[12], acc); acc = fmaf(m3.y, w[13], acc);
        acc = fmaf(m3.z, w[14], acc); acc = fmaf(m3.w, w[15], acc);

        out[gid] = fmaxf(acc, 0.0f);
    }
}

// ---------------------------------------------------------------------------
// Inputs (metadata order): r, src, dst, W1, b1, Wp, bp, Wf, bf
// ---------------------------------------------------------------------------
extern "C" void kernel_launch(void* const* d_in, const int* in_sizes, int n_in,
                              void* d_out, int out_size) {
    const float* r   = (const float*)d_in[0];
    const void*  src = d_in[1];
    const void*  dst = d_in[2];
    const float* W1  = (const float*)d_in[3];
    const float* b1  = (const float*)d_in[4];
    const float* Wp  = (const float*)d_in[5];
    const float* bp  = (const float*)d_in[6];
    const float* Wf  = (const float*)d_in[7];
    const float* bf  = (const float*)d_in[8];
    float*       out = (float*)d_out;

    int n = in_sizes[0] / NT;   // N nodes
    int E = in_sizes[1];        // edges
    if (n > N_MAX) n = N_MAX;

    k_init<<<(n * 4 + 255) / 256, 256>>>(src, E, n);
    k_compute_p<<<((n + 1) / 2 + 127) / 128, 128>>>(r, W1, b1, Wp, bp, n);
    {
        long long threads = (long long)((E + 1) / 2) * 4;
        int blocks = (int)((threads + 255) / 256);
        k_scatter<<<blocks, 256>>>(src, dst, E, n);
    }
    k_norm<<<(n * 4 + 255) / 256, 256>>>(n);
    k_final<<<3200, 256>>>(Wf, bf, out, n);
}

// round 11
// speedup vs baseline: 1.1304x; 1.0007x over previous
#include <cuda_runtime.h>
#include <cstdint>

#define NT 16     // NUM_TYPES
#define OD 128    // OUT_DIM
#define N_MAX 100000

typedef unsigned long long u64;

// Packed fp32x2 FMA (Blackwell FFMA2): d = a*b + c, two fp32 lanes per issue.
#define FMA2(d, a, b, c) \
    asm("fma.rn.f32x2 %0, %1, %2, %3;" : "=l"(d) : "l"(a), "l"(b), "l"(c))
#define PACK2(out, lo, hi) \
    asm("mov.b64 %0, {%1, %2};" : "=l"(out) : "f"(lo), "f"(hi))
#define UNPACK2(lo, hi, in) \
    asm("mov.b64 {%0, %1}, %2;" : "=f"(lo), "=f"(hi) : "l"(in))

// Scratch (allocation-free rule: __device__ globals). 16B-aligned for float4.
// g_p is stored PERMUTED within each 16-float row: position q*4+j holds
// logical element q+4j (q=0..3). Scatter lane q loads float4 #q =
// {p[q], p[q+4], p[q+8], p[q+12]} and REDs to natural msum positions q+4j;
// RED #j across the 4 lanes covers 16 CONTIGUOUS bytes (validated R8).
__device__ __align__(16) float g_p[N_MAX * NT];
__device__ __align__(16) float g_msum[N_MAX * NT];   // natural layout
__device__ int g_idx64;   // 1 if indices are int64, 0 if int32

// ---------------------------------------------------------------------------
// Init: detect index width + zero msum (float4 stores).
// ---------------------------------------------------------------------------
__global__ void k_init(const void* __restrict__ src, int E, int n) {
    int i = blockIdx.x * blockDim.x + threadIdx.x;
    if (i == 0) {
        const unsigned long long* p = (const unsigned long long*)src;
        int is64 = 1;
        int lim = (E / 2 < 16) ? E / 2 : 16;
        for (int k = 0; k < lim; k++) {
            if (p[k] > 0x7FFFFFFFULL) is64 = 0;
        }
        g_idx64 = is64;
    }
    int tot4 = n * 4;
    if (i < tot4) ((float4*)g_msum)[i] = make_float4(0.f, 0.f, 0.f, 0.f);
}

// ---------------------------------------------------------------------------
// p = softmax(relu(r@W1+b1) @ Wp + bp)   TWO nodes per thread, FFMA2 packed.
// z dot-product packs over k (r pairs pre-packed; W1t pairs adjacent in smem).
// acc packs over t (Wp pairs adjacent in smem; z duplicated per node).
// Output stored in the q/4-permuted layout (see g_p comment).
// ---------------------------------------------------------------------------
__global__ void __launch_bounds__(128) k_compute_p(
        const float* __restrict__ r,
        const float* __restrict__ W1,
        const float* __restrict__ b1,
        const float* __restrict__ Wp,
        const float* __restrict__ bp,
        int n) {
    __shared__ __align__(16) float sW1t[OD * NT];  // [j*16 + k] = W1[k*128 + j]
    __shared__ __align__(16) float sWp [OD * NT];  // [j*16 + t] = Wp[j*16 + t]
    __shared__ float sb1 [OD];
    __shared__ float sbp [NT];

    for (int i = threadIdx.x; i < OD * NT; i += blockDim.x) {
        int j = i >> 4, k = i & 15;
        sW1t[i] = W1[k * OD + j];
        sWp[i]  = Wp[i];
    }
    for (int i = threadIdx.x; i < OD; i += blockDim.x) sb1[i] = b1[i];
    if (threadIdx.x < NT) sbp[threadIdx.x] = bp[threadIdx.x];
    __syncthreads();

    int node0 = (blockIdx.x * blockDim.x + threadIdx.x) * 2;
    if (node0 >= n) return;
    bool two = (node0 + 1 < n);

    // r rows pre-packed over k: rA2[i] = (rA[2i], rA[2i+1])
    u64 rA2[8], rB2[8];
    {
        const float4* rp0 = (const float4*)(r + (size_t)node0 * NT);
#pragma unroll
        for (int i = 0; i < 4; i++) {
            float4 v = rp0[i];
            PACK2(rA2[i * 2 + 0], v.x, v.y);
            PACK2(rA2[i * 2 + 1], v.z, v.w);
        }
        if (two) {
            const float4* rp1 = (const float4*)(r + (size_t)(node0 + 1) * NT);
#pragma unroll
            for (int i = 0; i < 4; i++) {
                float4 v = rp1[i];
                PACK2(rB2[i * 2 + 0], v.x, v.y);
                PACK2(rB2[i * 2 + 1], v.z, v.w);
            }
        } else {
#pragma unroll
            for (int i = 0; i < 8; i++) rB2[i] = 0ULL;
        }
    }

    // accumulators packed over t: accA2[i] = (acc[2i], acc[2i+1]), init = bp
    u64 accA2[8], accB2[8];
#pragma unroll
    for (int i = 0; i < 8; i++) {
        u64 b2; PACK2(b2, sbp[2 * i], sbp[2 * i + 1]);
        accA2[i] = b2; accB2[i] = b2;
    }

#pragma unroll 2
    for (int j = 0; j < OD; j++) {
        // W1t row j: 16 floats = 8 packed k-pairs (adjacent in smem)
        const longlong2* w1p = (const longlong2*)(sW1t + j * NT);
        longlong2 wA = w1p[0], wB = w1p[1], wC = w1p[2], wD = w1p[3];

        u64 zA2 = 0ULL, zB2 = 0ULL;
        FMA2(zA2, rA2[0], (u64)wA.x, zA2); FMA2(zB2, rB2[0], (u64)wA.x, zB2);
        FMA2(zA2, rA2[1], (u64)wA.y, zA2); FMA2(zB2, rB2[1], (u64)wA.y, zB2);
        FMA2(zA2, rA2[2], (u64)wB.x, zA2); FMA2(zB2, rB2[2], (u64)wB.x, zB2);
        FMA2(zA2, rA2[3], (u64)wB.y, zA2); FMA2(zB2, rB2[3], (u64)wB.y, zB2);
        FMA2(zA2, rA2[4], (u64)wC.x, zA2); FMA2(zB2, rB2[4], (u64)wC.x, zB2);
        FMA2(zA2, rA2[5], (u64)wC.y, zA2); FMA2(zB2, rB2[5], (u64)wC.y, zB2);
        FMA2(zA2, rA2[6], (u64)wD.x, zA2); FMA2(zB2, rB2[6], (u64)wD.x, zB2);
        FMA2(zA2, rA2[7], (u64)wD.y, zA2); FMA2(zB2, rB2[7], (u64)wD.y, zB2);

        float bj = sb1[j];
        float zAl, zAh, zBl, zBh;
        UNPACK2(zAl, zAh, zA2);
        UNPACK2(zBl, zBh, zB2);
        float zA = fmaxf((zAl + zAh) + bj, 0.0f);
        float zB = fmaxf((zBl + zBh) + bj, 0.0f);
        u64 zzA, zzB;
        PACK2(zzA, zA, zA);
        PACK2(zzB, zB, zB);

        // Wp row j: 16 floats = 8 packed t-pairs (adjacent in smem)
        const longlong2* wpp = (const longlong2*)(sWp + j * NT);
        longlong2 pA = wpp[0], pB = wpp[1], pC = wpp[2], pD = wpp[3];

        FMA2(accA2[0], zzA, (u64)pA.x, accA2[0]); FMA2(accB2[0], zzB, (u64)pA.x, accB2[0]);
        FMA2(accA2[1], zzA, (u64)pA.y, accA2[1]); FMA2(accB2[1], zzB, (u64)pA.y, accB2[1]);
        FMA2(accA2[2], zzA, (u64)pB.x, accA2[2]); FMA2(accB2[2], zzB, (u64)pB.x, accB2[2]);
        FMA2(accA2[3], zzA, (u64)pB.y, accA2[3]); FMA2(accB2[3], zzB, (u64)pB.y, accB2[3]);
        FMA2(accA2[4], zzA, (u64)pC.x, accA2[4]); FMA2(accB2[4], zzB, (u64)pC.x, accB2[4]);
        FMA2(accA2[5], zzA, (u64)pC.y, accA2[5]); FMA2(accB2[5], zzB, (u64)pC.y, accB2[5]);
        FMA2(accA2[6], zzA, (u64)pD.x, accA2[6]); FMA2(accB2[6], zzB, (u64)pD.x, accB2[6]);
        FMA2(accA2[7], zzA, (u64)pD.y, accA2[7]); FMA2(accB2[7], zzB, (u64)pD.y, accB2[7]);
    }

    // unpack accumulators
    float accA[NT], accB[NT];
#pragma unroll
    for (int i = 0; i < 8; i++) {
        UNPACK2(accA[2 * i], accA[2 * i + 1], accA2[i]);
        UNPACK2(accB[2 * i], accB[2 * i + 1], accB2[i]);
    }

    {
        float m = accA[0];
#pragma unroll
        for (int t = 1; t < NT; t++) m = fmaxf(m, accA[t]);
        float s = 0.0f;
#pragma unroll
        for (int t = 0; t < NT; t++) { accA[t] = __expf(accA[t] - m); s += accA[t]; }
        float inv = 1.0f / s;
        float4* o = (float4*)(g_p + (size_t)node0 * NT);
        // PERMUTED store: float4 #q = {p[q], p[q+4], p[q+8], p[q+12]}
        o[0] = make_float4(accA[0]*inv, accA[4]*inv, accA[8]*inv,  accA[12]*inv);
        o[1] = make_float4(accA[1]*inv, accA[5]*inv, accA[9]*inv,  accA[13]*inv);
        o[2] = make_float4(accA[2]*inv, accA[6]*inv, accA[10]*inv, accA[14]*inv);
        o[3] = make_float4(accA[3]*inv, accA[7]*inv, accA[11]*inv, accA[15]*inv);
    }
    if (two) {
        float m = accB[0];
#pragma unroll
        for (int t = 1; t < NT; t++) m = fmaxf(m, accB[t]);
        float s = 0.0f;
#pragma unroll
        for (int t = 0; t < NT; t++) { accB[t] = __expf(accB[t] - m); s += accB[t]; }
        float inv = 1.0f / s;
        float4* o = (float4*)(g_p + (size_t)(node0 + 1) * NT);
        o[0] = make_float4(accB[0]*inv, accB[4]*inv, accB[8]*inv,  accB[12]*inv);
        o[1] = make_float4(accB[1]*inv, accB[5]*inv, accB[9]*inv,  accB[13]*inv);
        o[2] = make_float4(accB[2]*inv, accB[6]*inv, accB[10]*inv, accB[14]*inv);
        o[3] = make_float4(accB[3]*inv, accB[7]*inv, accB[11]*inv, accB[15]*inv);
    }
}

// ---------------------------------------------------------------------------
// Scatter: msum[dst] += p[src].  4 lanes per edge, 2 edges per thread
// (validated R10). RED #j across an edge's 4 lanes covers 16 contiguous
// bytes. No degree atomics (row-sum trick).
// ---------------------------------------------------------------------------
__global__ void k_scatter(const void* __restrict__ srcv,
                          const void* __restrict__ dstv,
                          int E, int n) {
    int gid = blockIdx.x * blockDim.x + threadIdx.x;
    int pair = gid >> 2;
    int e0 = pair * 2;
    if (e0 >= E) return;
    int q = gid & 3;
    bool has2 = (e0 + 1 < E);

    int s0, d0, s1 = 0, d1 = 0;
    if (g_idx64) {
        const longlong2* ps = (const longlong2*)srcv;
        const longlong2* pd = (const longlong2*)dstv;
        longlong2 sv = ps[pair];
        longlong2 dv = pd[pair];
        s0 = (int)sv.x; s1 = (int)sv.y;
        d0 = (int)dv.x; d1 = (int)dv.y;
    } else {
        const int2* ps = (const int2*)srcv;
        const int2* pd = (const int2*)dstv;
        int2 sv = ps[pair];
        int2 dv = pd[pair];
        s0 = sv.x; s1 = sv.y;
        d0 = dv.x; d1 = dv.y;
    }
    s0 = min(max(s0, 0), n - 1);
    d0 = min(max(d0, 0), n - 1);

    const float4 v0 = __ldg((const float4*)(g_p + (size_t)s0 * NT + q * 4));
    float* row0 = g_msum + (size_t)d0 * NT + q;
    atomicAdd(row0 + 0,  v0.x);
    atomicAdd(row0 + 4,  v0.y);
    atomicAdd(row0 + 8,  v0.z);
    atomicAdd(row0 + 12, v0.w);

    if (has2) {
        s1 = min(max(s1, 0), n - 1);
        d1 = min(max(d1, 0), n - 1);
        const float4 v1 = __ldg((const float4*)(g_p + (size_t)s1 * NT + q * 4));
        float* row1 = g_msum + (size_t)d1 * NT + q;
        atomicAdd(row1 + 0,  v1.x);
        atomicAdd(row1 + 4,  v1.y);
        atomicAdd(row1 + 8,  v1.z);
        atomicAdd(row1 + 12, v1.w);
    }
}

// ---------------------------------------------------------------------------
// Normalize: msum[node] *= 1/max(round(rowsum),1).  4 threads per node.
// ---------------------------------------------------------------------------
__global__ void k_norm(int n) {
    int gid = blockIdx.x * blockDim.x + threadIdx.x;
    int node = gid >> 2;
    if (node >= n) return;

    float4* p = (float4*)g_msum + (size_t)gid;
    float4 v = *p;
    float s = (v.x + v.y) + (v.z + v.w);
    s += __shfl_xor_sync(0xffffffffu, s, 1);
    s += __shfl_xor_sync(0xffffffffu, s, 2);
    float invd = 1.0f / fmaxf(nearbyintf(s), 1.0f);
    v.x *= invd; v.y *= invd; v.z *= invd; v.w *= invd;
    *p = v;
}

// ---------------------------------------------------------------------------
// out = relu(n_dist @ Wf + bf)   (n_dist = pre-normalized msum)
// j = tid&127 is loop-invariant: the 16 weights live in REGISTERS.
// ---------------------------------------------------------------------------
__global__ void __launch_bounds__(256) k_final(
        const float* __restrict__ Wf,
        const float* __restrict__ bf,
        float* __restrict__ out,
        int n) {
    int j = threadIdx.x & 127;
    float w[NT];
#pragma unroll
    for (int t = 0; t < NT; t++) w[t] = Wf[t * OD + j];
    float bj = bf[j];

    int total  = n * OD;
    int stride = gridDim.x * blockDim.x;
    for (int gid = blockIdx.x * blockDim.x + threadIdx.x; gid < total; gid += stride) {
        int node = gid >> 7;

        const float4* ms = (const float4*)(g_msum + (size_t)node * NT);
        float4 m0 = ms[0], m1 = ms[1], m2 = ms[2], m3 = ms[3];

        float acc = bj;
        acc = fmaf(m0.x, w[0],  acc); acc = fmaf(m0.y, w[1],  acc);
        acc = fmaf(m0.z, w[2],  acc); acc = fmaf(m0.w, w[3],  acc);
        acc = fmaf(m1.x, w[4],  acc); acc = fmaf(m1.y, w[5],  acc);
        acc = fmaf(m1.z, w[6],  acc); acc = fmaf(m1.w, w[7],  acc);
        acc = fmaf(m2.x, w[8],  acc); acc = fmaf(m2.y, w[9],  acc);
        acc = fmaf(m2.z, w[10], acc); acc = fmaf(m2.w, w[11], acc);
        acc = fmaf(m3.x, w[12], acc); acc = fmaf(m3.y, w[13], acc);
        acc = fmaf(m3.z, w[14], acc); acc = fmaf(m3.w, w[15], acc);

        out[gid] = fmaxf(acc, 0.0f);
    }
}

// ---------------------------------------------------------------------------
// Inputs (metadata order): r, src, dst, W1, b1, Wp, bp, Wf, bf
// ---------------------------------------------------------------------------
extern "C" void kernel_launch(void* const* d_in, const int* in_sizes, int n_in,
                              void* d_out, int out_size) {
    const float* r   = (const float*)d_in[0];
    const void*  src = d_in[1];
    const void*  dst = d_in[2];
    const float* W1  = (const float*)d_in[3];
    const float* b1  = (const float*)d_in[4];
    const float* Wp  = (const float*)d_in[5];
    const float* bp  = (const float*)d_in[6];
    const float* Wf  = (const float*)d_in[7];
    const float* bf  = (const float*)d_in[8];
    float*       out = (float*)d_out;

    int n = in_sizes[0] / NT;
    int E = in_sizes[1];
    if (n > N_MAX) n = N_MAX;

    k_init<<<(n * 4 + 255) / 256, 256>>>(src, E, n);
    k_compute_p<<<((n + 1) / 2 + 127) / 128, 128>>>(r, W1, b1, Wp, bp, n);
    {
        long long threads = (long long)((E + 1) / 2) * 4;
        int blocks = (int)((threads + 255) / 256);
        k_scatter<<<blocks, 256>>>(src, dst, E, n);
    }
    k_norm<<<(n * 4 + 255) / 256, 256>>>(n);
    k_final<<<3200, 256>>>(Wf, bf, out, n);
}